// round 6
// baseline (speedup 1.0000x reference)
#include <cuda_runtime.h>

// EMA scan: out[b,t,d] = a*out[b,t-1,d] + (1-a)*x[b,t,d], out[b,-1,d]=0
// Shapes fixed: B=4, S=4096, D=2048, fp32.
//
// Single fused persistent kernel. Each thread owns one float4 lane x 8
// timesteps per round, held in REGISTERS across a software grid barrier, so
// x is read from DRAM exactly once and out written exactly once (268 MB,
// the traffic floor). 16 rounds; per round: prefetch next tile, local scan,
// publish chunk ends, grid barrier, 2048 threads chain carries, grid
// barrier, finish scan from registers, store.
//
// Grid = 256 CTAs x 256 thr with __launch_bounds__(256,2): >=2 CTAs/SM
// guaranteed => 296 >= 256 co-resident => barrier is deadlock-free. The
// sense-reversing generation counter is monotonic => no reset needed,
// deterministic across graph replays.

#define B 4
#define S 4096
#define D 2048
#define D4 (D / 4)
#define LANES (B * D4)          // 2048 float4 lanes
#define TPB 256
#define NCTA 256
#define NTHREADS (NCTA * TPB)   // 65536
#define CHUNK 8                 // timesteps per tile (32 data regs)
#define CPR (NTHREADS / LANES)  // 32 chunks per round
#define TSPAN (CPR * CHUNK)     // 256 timesteps per round
#define ROUNDS (S / TSPAN)      // 16

constexpr float ALPHA = 0.99f;
constexpr float ONEM  = 0.01f;

constexpr float pow_alpha(int n) {
    double r = 1.0;
    for (int i = 0; i < n; ++i) r *= 0.99;
    return (float)r;
}
constexpr float DEC = pow_alpha(CHUNK);   // alpha^8

__device__ __forceinline__ float4 ema_step(float4 e, float4 v) {
    e.x = fmaf(ALPHA, e.x, ONEM * v.x);
    e.y = fmaf(ALPHA, e.y, ONEM * v.y);
    e.z = fmaf(ALPHA, e.z, ONEM * v.z);
    e.w = fmaf(ALPHA, e.w, ONEM * v.w);
    return e;
}

// Scratch (1 MB each) + barrier state.
__device__ float4 g_ends [CPR * LANES];
__device__ float4 g_carry[CPR * LANES];
__device__ float4 g_run  [LANES];
__device__ unsigned g_barcnt = 0;
__device__ volatile unsigned g_bargen = 0;

__device__ __forceinline__ void grid_barrier() {
    __syncthreads();
    if (threadIdx.x == 0) {
        __threadfence();
        unsigned my = g_bargen;
        __threadfence();
        if (atomicAdd(&g_barcnt, 1u) == (unsigned)(NCTA - 1)) {
            g_barcnt = 0;
            __threadfence();
            g_bargen = my + 1;   // release
        } else {
            while (g_bargen == my) { }
            __threadfence();
        }
    }
    __syncthreads();
}

__global__ void __launch_bounds__(TPB, 2)
ema_fused(const float4* __restrict__ x4, float4* __restrict__ out4) {
    const int g    = blockIdx.x * TPB + threadIdx.x;   // 0..65535
    const int lane = g & (LANES - 1);                  // float4 lane
    const int ci   = g >> 11;                          // chunk-in-round 0..31
    const int b    = lane >> 9;                        // batch
    const int d4   = lane & (D4 - 1);

    float4 v[CHUNK], vn[CHUNK];

    // Prologue: load round-0 tile.
    {
        const size_t base = ((size_t)b * S + (size_t)ci * CHUNK) * D4 + d4;
#pragma unroll
        for (int j = 0; j < CHUNK; ++j) v[j] = x4[base + (size_t)j * D4];
    }

#pragma unroll 1
    for (int r = 0; r < ROUNDS; ++r) {
        const size_t t0 = (size_t)r * TSPAN + (size_t)ci * CHUNK;

        // Prefetch next round's tile (independent; stays in flight across
        // the barriers + carry chain so DRAM never idles).
        if (r + 1 < ROUNDS) {
            const size_t nb = ((size_t)b * S + t0 + TSPAN) * D4 + d4;
#pragma unroll
            for (int j = 0; j < CHUNK; ++j) vn[j] = x4[nb + (size_t)j * D4];
        }

        // Local scan from 0 -> chunk end.
        float4 e = make_float4(0.f, 0.f, 0.f, 0.f);
#pragma unroll
        for (int j = 0; j < CHUNK; ++j) e = ema_step(e, v[j]);
        g_ends[ci * LANES + lane] = e;

        grid_barrier();

        // Carry chain over this round's 32 chunks (one thread per lane).
        if (g < LANES) {
            float4 E;
            if (r == 0) E = make_float4(0.f, 0.f, 0.f, 0.f);
            else        E = g_run[g];
#pragma unroll
            for (int k0 = 0; k0 < CPR; k0 += 4) {
                float4 ee[4];
#pragma unroll
                for (int j = 0; j < 4; ++j) ee[j] = g_ends[(k0 + j) * LANES + g];
#pragma unroll
                for (int j = 0; j < 4; ++j) {
                    g_carry[(k0 + j) * LANES + g] = E;
                    E.x = fmaf(DEC, E.x, ee[j].x);
                    E.y = fmaf(DEC, E.y, ee[j].y);
                    E.z = fmaf(DEC, E.z, ee[j].z);
                    E.w = fmaf(DEC, E.w, ee[j].w);
                }
            }
            g_run[g] = E;
        }

        grid_barrier();

        // Finish: exact recurrence seeded with carry, from registers.
        float4 ema = g_carry[ci * LANES + lane];
        const size_t ob = ((size_t)b * S + t0) * D4 + d4;
#pragma unroll
        for (int j = 0; j < CHUNK; ++j) {
            ema = ema_step(ema, v[j]);
            __stcs(&out4[ob + (size_t)j * D4], ema);
        }

#pragma unroll
        for (int j = 0; j < CHUNK; ++j) v[j] = vn[j];
    }
}

extern "C" void kernel_launch(void* const* d_in, const int* in_sizes, int n_in,
                              void* d_out, int out_size) {
    const float4* x4 = (const float4*)d_in[0];
    float4* out4 = (float4*)d_out;
    ema_fused<<<NCTA, TPB>>>(x4, out4);
}

// round 7
// speedup vs baseline: 2.2562x; 2.2562x over previous
#include <cuda_runtime.h>

// EMA scan: out[b,t,d] = a*out[b,t-1,d] + (1-a)*x[b,t,d], out[b,-1,d]=0
// Shapes fixed: B=4, S=4096, D=2048, fp32.
//
// Chunked 3-pass scan, float4 lanes, 2 L2-sized segments (67MB < 126MB L2).
// CHUNK=16 -> 2048 CTAs (8192 warps, ~55/SM) per pass: the occupancy regime
// that measured 68% DRAM in round 1. Pass3 walks chunks in REVERSE so its
// x re-read starts on the most-recently-touched (LRU-hottest) lines from
// pass1; x re-read uses __ldcs (last use) and outputs __stcs so writes
// don't evict the resident segment.

#define B 4
#define S 4096
#define D 2048
#define D4 (D / 4)            // 512 float4 lanes
#define SEG_T 2048            // timesteps per segment
#define NSEG (S / SEG_T)      // 2
#define CHUNK 16              // timesteps per chunk
#define CPS (SEG_T / CHUNK)   // 128 chunks per segment
#define TPB 128

constexpr float ALPHA = 0.99f;
constexpr float ONEM  = 0.01f;

constexpr float pow_alpha(int n) {
    double r = 1.0;
    for (int i = 0; i < n; ++i) r *= 0.99;
    return (float)r;
}
constexpr float DEC = pow_alpha(CHUNK);   // alpha^16

__device__ __forceinline__ float4 ema_step(float4 e, float4 v) {
    e.x = fmaf(ALPHA, e.x, ONEM * v.x);
    e.y = fmaf(ALPHA, e.y, ONEM * v.y);
    e.z = fmaf(ALPHA, e.z, ONEM * v.z);
    e.w = fmaf(ALPHA, e.w, ONEM * v.w);
    return e;
}

// Scratch (per-segment lifetime; stream-serialized launches).
__device__ float4 g_ends [B * CPS * D4];   // chunk-local end EMAs (4 MB)
__device__ float4 g_carry[B * CPS * D4];   // carry at chunk start (4 MB)
__device__ float4 g_run  [B * D4];         // running carry across segments

// ---------------------------------------------------------------------------
// Pass 1: local EMA from 0 over CHUNK steps; store chunk-end value.
// grid: (D4/TPB, CPS, B) = (4, 128, 4) = 2048 CTAs, 8192 warps.
// ---------------------------------------------------------------------------
__global__ void __launch_bounds__(TPB) ema_pass1(const float4* __restrict__ x4,
                                                 int seg) {
    const int d4 = blockIdx.x * TPB + threadIdx.x;
    const int c = blockIdx.y;
    const int b = blockIdx.z;

    const size_t base =
        ((size_t)b * S + (size_t)seg * SEG_T + (size_t)c * CHUNK) * D4 + d4;

    float4 e = make_float4(0.f, 0.f, 0.f, 0.f);

#pragma unroll
    for (int t0 = 0; t0 < CHUNK; t0 += 8) {
        float4 v[8];
#pragma unroll
        for (int j = 0; j < 8; ++j) v[j] = x4[base + (size_t)(t0 + j) * D4];
#pragma unroll
        for (int j = 0; j < 8; ++j) e = ema_step(e, v[j]);
    }

    g_ends[((size_t)b * CPS + c) * D4 + d4] = e;
}

// ---------------------------------------------------------------------------
// Pass 2: chain carries through this segment's chunks (scalar lanes; 8192
// threads, CPS serial steps, batched prefetch). Updates g_run.
// ---------------------------------------------------------------------------
__global__ void __launch_bounds__(256) ema_pass2(int seg) {
    const int i = blockIdx.x * blockDim.x + threadIdx.x;  // 0..B*D-1
    const int b = i / D;
    const int dd = i % D;

    const float* ends = (const float*)g_ends;
    float* carry = (float*)g_carry;
    float* run = (float*)g_run;

    float E = (seg == 0) ? 0.0f : run[i];

#pragma unroll 4
    for (int c0 = 0; c0 < CPS; c0 += 8) {
        float e[8];
#pragma unroll
        for (int j = 0; j < 8; ++j)
            e[j] = ends[((size_t)b * CPS + c0 + j) * D + dd];
#pragma unroll
        for (int j = 0; j < 8; ++j) {
            carry[((size_t)b * CPS + c0 + j) * D + dd] = E;
            E = fmaf(DEC, E, e[j]);
        }
    }
    run[i] = E;
}

// ---------------------------------------------------------------------------
// Pass 3: exact recurrence seeded with carry. Chunks walked in REVERSE
// launch order (c = CPS-1-blockIdx.y) so the earliest-scheduled CTAs re-read
// the lines pass1 touched last (still L2-resident). x read with __ldcs
// (last use), out written __stcs (evict-first).
// ---------------------------------------------------------------------------
__global__ void __launch_bounds__(TPB) ema_pass3(const float4* __restrict__ x4,
                                                 float4* __restrict__ out4,
                                                 int seg) {
    const int d4 = blockIdx.x * TPB + threadIdx.x;
    const int c = (CPS - 1) - blockIdx.y;
    const int b = blockIdx.z;

    const size_t base =
        ((size_t)b * S + (size_t)seg * SEG_T + (size_t)c * CHUNK) * D4 + d4;

    float4 ema = g_carry[((size_t)b * CPS + c) * D4 + d4];

#pragma unroll
    for (int t0 = 0; t0 < CHUNK; t0 += 8) {
        float4 v[8];
#pragma unroll
        for (int j = 0; j < 8; ++j)
            v[j] = __ldcs(&x4[base + (size_t)(t0 + j) * D4]);
        float4 r[8];
#pragma unroll
        for (int j = 0; j < 8; ++j) {
            ema = ema_step(ema, v[j]);
            r[j] = ema;
        }
#pragma unroll
        for (int j = 0; j < 8; ++j)
            __stcs(&out4[base + (size_t)(t0 + j) * D4], r[j]);
    }
}

extern "C" void kernel_launch(void* const* d_in, const int* in_sizes, int n_in,
                              void* d_out, int out_size) {
    const float4* x4 = (const float4*)d_in[0];
    float4* out4 = (float4*)d_out;

    dim3 g1(D4 / TPB, CPS, B);            // (4, 128, 4) = 2048 CTAs
    for (int seg = 0; seg < NSEG; ++seg) {
        ema_pass1<<<g1, TPB>>>(x4, seg);
        ema_pass2<<<(B * D) / 256, 256>>>(seg);
        ema_pass3<<<g1, TPB>>>(x4, out4, seg);
    }
}

// round 8
// speedup vs baseline: 2.4462x; 1.0842x over previous
#include <cuda_runtime.h>

// EMA scan: out[b,t,d] = a*out[b,t-1,d] + (1-a)*x[b,t,d], out[b,-1,d]=0
// Shapes fixed: B=4, S=4096, D=2048, fp32.
//
// Chunked 3-pass scan in the round-1 kernel shape (scalar lanes, TPB=256,
// 8-deep hoisted load batches, 1024 CTAs/pass) + round-5 L2 segmentation
// (2 segments of 2048 timesteps = 67MB, fits L2). Pass1 reads x with
// default caching (lines persist in L2); pass3 re-reads x (__ldcs, last
// use) and writes out with __stcs (evict-first, minimal pollution).

#define B 4
#define S 4096
#define D 2048
#define SEG_T 2048            // timesteps per segment (67MB < 126MB L2)
#define NSEG (S / SEG_T)      // 2
#define CHUNK 64              // timesteps per chunk
#define CPS (SEG_T / CHUNK)   // 32 chunks per segment
#define TPB 256

constexpr float ALPHA = 0.99f;
constexpr float ONEM  = 0.01f;

constexpr float pow_alpha(int n) {
    double r = 1.0;
    for (int i = 0; i < n; ++i) r *= 0.99;
    return (float)r;
}
constexpr float DEC = pow_alpha(CHUNK);   // alpha^64

// Scratch (per-segment lifetime; stream-serialized launches).
__device__ float g_ends [B * CPS * D];   // chunk-local end EMAs
__device__ float g_carry[B * CPS * D];   // carry (global EMA at chunk start)
__device__ float g_run  [B * D];         // running carry across segments

// ---------------------------------------------------------------------------
// Pass 1: local EMA from 0 over CHUNK steps; store chunk-end value.
// grid: (D/TPB, CPS, B) = (8, 32, 4) = 1024 CTAs, 8192 warps.
// ---------------------------------------------------------------------------
__global__ void __launch_bounds__(TPB) ema_pass1(const float* __restrict__ x,
                                                 int seg) {
    const int d = blockIdx.x * TPB + threadIdx.x;
    const int c = blockIdx.y;
    const int b = blockIdx.z;

    const float* xp =
        x + ((size_t)b * S + (size_t)seg * SEG_T + (size_t)c * CHUNK) * D + d;

    float e = 0.0f;
    const float a = ALPHA, om = ONEM;

#pragma unroll 4
    for (int t0 = 0; t0 < CHUNK; t0 += 8) {
        float v[8];
#pragma unroll
        for (int j = 0; j < 8; ++j) v[j] = xp[(size_t)(t0 + j) * D];
#pragma unroll
        for (int j = 0; j < 8; ++j) e = fmaf(a, e, om * v[j]);
    }

    g_ends[((size_t)b * CPS + c) * D + d] = e;
}

// ---------------------------------------------------------------------------
// Pass 2: chain carries through this segment's chunks; update running carry.
// 8192 threads, CPS=32 serial steps, batched prefetch.
// ---------------------------------------------------------------------------
__global__ void __launch_bounds__(256) ema_pass2(int seg) {
    const int i = blockIdx.x * blockDim.x + threadIdx.x;  // 0..B*D-1
    const int b = i / D;
    const int dd = i % D;

    float E = (seg == 0) ? 0.0f : g_run[i];

#pragma unroll
    for (int c0 = 0; c0 < CPS; c0 += 8) {
        float e[8];
#pragma unroll
        for (int j = 0; j < 8; ++j)
            e[j] = g_ends[((size_t)b * CPS + c0 + j) * D + dd];
#pragma unroll
        for (int j = 0; j < 8; ++j) {
            g_carry[((size_t)b * CPS + c0 + j) * D + dd] = E;
            E = fmaf(DEC, E, e[j]);
        }
    }
    g_run[i] = E;
}

// ---------------------------------------------------------------------------
// Pass 3: exact recurrence seeded with carry; x re-read (L2-hot from pass1,
// __ldcs = last use), outputs written evict-first (__stcs).
// grid identical to pass1.
// ---------------------------------------------------------------------------
__global__ void __launch_bounds__(TPB) ema_pass3(const float* __restrict__ x,
                                                 float* __restrict__ out,
                                                 int seg) {
    const int d = blockIdx.x * TPB + threadIdx.x;
    const int c = blockIdx.y;
    const int b = blockIdx.z;

    const size_t base =
        ((size_t)b * S + (size_t)seg * SEG_T + (size_t)c * CHUNK) * D + d;
    const float* xp = x + base;
    float* op = out + base;

    float ema = g_carry[((size_t)b * CPS + c) * D + d];
    const float a = ALPHA, om = ONEM;

#pragma unroll 4
    for (int t0 = 0; t0 < CHUNK; t0 += 8) {
        float v[8];
#pragma unroll
        for (int j = 0; j < 8; ++j)
            v[j] = __ldcs(&xp[(size_t)(t0 + j) * D]);
        float r[8];
#pragma unroll
        for (int j = 0; j < 8; ++j) {
            ema = fmaf(a, ema, om * v[j]);
            r[j] = ema;
        }
#pragma unroll
        for (int j = 0; j < 8; ++j)
            __stcs(&op[(size_t)(t0 + j) * D], r[j]);
    }
}

extern "C" void kernel_launch(void* const* d_in, const int* in_sizes, int n_in,
                              void* d_out, int out_size) {
    const float* x = (const float*)d_in[0];
    float* out = (float*)d_out;

    dim3 g1(D / TPB, CPS, B);             // (8, 32, 4) = 1024 CTAs
    for (int seg = 0; seg < NSEG; ++seg) {
        ema_pass1<<<g1, TPB>>>(x, seg);
        ema_pass2<<<(B * D) / 256, 256>>>(seg);
        ema_pass3<<<g1, TPB>>>(x, out, seg);
    }
}